// round 14
// baseline (speedup 1.0000x reference)
#include <cuda_runtime.h>
#include <cuda_bf16.h>
#include <cstdint>

#define S_LEN 8192
#define NBATCH 8
#define DIM 128
#define NB 32
#define NROWS (NBATCH*S_LEN)
#define LDE 136      // bf16 elems per 272B operand row
#define N_ITEMS (8 + 512 + 256)

// ---------------- scratch (static device arrays; allocation-free rule) -----
__device__ __align__(16) float g_C[(size_t)NBATCH*NB*2*DIM*DIM]; // partial C' per (chunk,half)
__device__ __align__(16) float g_eK[(size_t)NBATCH*NB*2*DIM];    // edge k rows (biased)
__device__ __align__(16) float g_eV[(size_t)NBATCH*NB*2*DIM];
__device__ __align__(16) __nv_bfloat16 g_w_hi[3*DIM*DIM];        // Wq,Wk,Wv (row-major [h][d])
__device__ __align__(16) __nv_bfloat16 g_w_lo[3*DIM*DIM];
__device__ __align__(16) __nv_bfloat16 g_wt_hi[DIM*DIM];         // Wq^T ([d][hq])
__device__ __align__(16) __nv_bfloat16 g_wt_lo[DIM*DIM];
__device__ int g_item;                    // work-queue counter
__device__ int g_wcnt;                    // W conversion done counter (0..8)
__device__ int g_done[NBATCH*NB];         // per-chunk half counters (0..2)

// smem regions: 3 x 68KB operand regions + ext
#define R_X 0
#define R_XH 0
#define R_XL 34816
#define R_W 69632
#define R_WH 69632
#define R_WL 104448
#define R_V 139264
#define R_VH 139264
#define R_VL 174080
#define R_EXT 208896
#define SMEM_SZ (R_EXT+3072)

// ---------------- helpers ---------------------------------------------------
__device__ __forceinline__ unsigned smem_u32(const void* p){
    unsigned a; asm("{ .reg .u64 t; cvta.to.shared.u64 t, %1; cvt.u32.u64 %0, t; }":"=r"(a):"l"(p)); return a;
}
__device__ __forceinline__ void ldm4(unsigned* r, unsigned addr){
    asm volatile("ldmatrix.sync.aligned.m8n8.x4.shared.b16 {%0,%1,%2,%3}, [%4];"
        : "=r"(r[0]),"=r"(r[1]),"=r"(r[2]),"=r"(r[3]) : "r"(addr));
}
__device__ __forceinline__ void ldm4t(unsigned* r, unsigned addr){
    asm volatile("ldmatrix.sync.aligned.m8n8.x4.trans.shared.b16 {%0,%1,%2,%3}, [%4];"
        : "=r"(r[0]),"=r"(r[1]),"=r"(r[2]),"=r"(r[3]) : "r"(addr));
}
__device__ __forceinline__ void mma16816(float* d, const unsigned* a, unsigned b0, unsigned b1){
    asm volatile("mma.sync.aligned.m16n8k16.row.col.f32.bf16.bf16.f32 "
        "{%0,%1,%2,%3}, {%4,%5,%6,%7}, {%8,%9}, {%0,%1,%2,%3};"
        : "+f"(d[0]),"+f"(d[1]),"+f"(d[2]),"+f"(d[3])
        : "r"(a[0]),"r"(a[1]),"r"(a[2]),"r"(a[3]), "r"(b0),"r"(b1));
}
__device__ __forceinline__ void cpa(unsigned d, const void* s){
    asm volatile("cp.async.cg.shared.global [%0], [%1], 16;"::"r"(d),"l"(s));
}
#define CPC() asm volatile("cp.async.commit_group;":::"memory")
#define CPW(n) asm volatile("cp.async.wait_group %0;"::"n"(n):"memory")

// merged 3-pass (AhBh + AhBl + AlBh), non-trans operands [row][k]
__device__ __forceinline__ void pass3N(unsigned aH, unsigned aL, unsigned bH, unsigned bL,
                                       float acc[2][8][4], int wr, int wc, int lane){
    unsigned aOff = (unsigned)((wr*32 + (lane&15))*272) + ((lane>>4)<<4);
    unsigned bOff = (unsigned)((wc*64 + (lane&7) + ((lane>>4)<<3))*272) + (((lane>>3)&1)<<4);
#pragma unroll
    for(int ks=0; ks<8; ks++){
        unsigned ah0[4], ah1[4], al0[4], al1[4], bh[4][4], bl[4][4];
        ldm4(ah0, aH + aOff + ks*32);
        ldm4(ah1, aH + aOff + 16*272 + ks*32);
        ldm4(al0, aL + aOff + ks*32);
        ldm4(al1, aL + aOff + 16*272 + ks*32);
#pragma unroll
        for(int n2=0; n2<4; n2++){
            ldm4(bh[n2], bH + bOff + n2*16*272 + ks*32);
            ldm4(bl[n2], bL + bOff + n2*16*272 + ks*32);
        }
#pragma unroll
        for(int nt=0; nt<8; nt++){
            unsigned b0 = bh[nt>>1][(nt&1)*2], b1 = bh[nt>>1][(nt&1)*2+1];
            mma16816(acc[0][nt], ah0, b0, b1);
            mma16816(acc[1][nt], ah1, b0, b1);
        }
#pragma unroll
        for(int nt=0; nt<8; nt++){
            unsigned c0 = bl[nt>>1][(nt&1)*2], c1 = bl[nt>>1][(nt&1)*2+1];
            mma16816(acc[0][nt], ah0, c0, c1);
            mma16816(acc[1][nt], ah1, c0, c1);
        }
#pragma unroll
        for(int nt=0; nt<8; nt++){
            unsigned b0 = bh[nt>>1][(nt&1)*2], b1 = bh[nt>>1][(nt&1)*2+1];
            mma16816(acc[0][nt], al0, b0, b1);
            mma16816(acc[1][nt], al1, b0, b1);
        }
    }
}
// merged 3-pass, trans operands stored [t][m]/[t][n]
__device__ __forceinline__ void pass3T(unsigned aH, unsigned aL, unsigned bH, unsigned bL,
                                       float acc[2][8][4], int wr, int wc, int lane){
    unsigned row = (unsigned)((lane&7) + ((lane>>4)<<3));
    unsigned csel = (unsigned)((lane>>3)&1);
    unsigned aOff = row*272 + (unsigned)(wr*32 + csel*8)*2;
    unsigned bOff = row*272 + (unsigned)(wc*64 + csel*8)*2;
#pragma unroll
    for(int ks=0; ks<8; ks++){
        unsigned base = (unsigned)ks*4352;
        unsigned ah0[4], ah1[4], al0[4], al1[4], bh[4][4], bl[4][4];
        ldm4t(ah0, aH + aOff + base);
        ldm4t(ah1, aH + aOff + base + 32);
        ldm4t(al0, aL + aOff + base);
        ldm4t(al1, aL + aOff + base + 32);
#pragma unroll
        for(int g=0; g<4; g++){
            ldm4t(bh[g], bH + bOff + base + g*32);
            ldm4t(bl[g], bL + bOff + base + g*32);
        }
#pragma unroll
        for(int nt=0; nt<8; nt++){
            int g=nt>>1, sub=nt&1;
            unsigned b0 = bh[g][sub], b1 = bh[g][sub+2];
            mma16816(acc[0][nt], ah0, b0, b1);
            mma16816(acc[1][nt], ah1, b0, b1);
        }
#pragma unroll
        for(int nt=0; nt<8; nt++){
            int g=nt>>1, sub=nt&1;
            unsigned c0 = bl[g][sub], c1 = bl[g][sub+2];
            mma16816(acc[0][nt], ah0, c0, c1);
            mma16816(acc[1][nt], ah1, c0, c1);
        }
#pragma unroll
        for(int nt=0; nt<8; nt++){
            int g=nt>>1, sub=nt&1;
            unsigned b0 = bh[g][sub], b1 = bh[g][sub+2];
            mma16816(acc[0][nt], al0, b0, b1);
            mma16816(acc[1][nt], al1, b0, b1);
        }
    }
}
__device__ __forceinline__ void zacc(float acc[2][8][4]){
#pragma unroll
    for(int a=0;a<2;a++)
#pragma unroll
    for(int b=0;b<8;b++){acc[a][b][0]=acc[a][b][1]=acc[a][b][2]=acc[a][b][3]=0.f;}
}
__device__ __forceinline__ void frag_to_op(float acc[2][8][4], __nv_bfloat16* Oh, __nv_bfloat16* Ol,
                                           const float* bias, float* erow, int ewhich,
                                           int wr, int wc, int lane){
#pragma unroll
    for(int mt=0; mt<2; mt++)
#pragma unroll
    for(int nt=0; nt<8; nt++){
        int c = wc*64 + (lane&3)*2 + nt*8;
        float b0 = bias? bias[c]   : 0.f;
        float b1 = bias? bias[c+1] : 0.f;
#pragma unroll
        for(int hh=0; hh<2; hh++){
            int r = wr*32 + (lane>>2) + mt*16 + hh*8;
            float v0 = acc[mt][nt][hh*2]   + b0;
            float v1 = acc[mt][nt][hh*2+1] + b1;
            __nv_bfloat162 H, L;
            H.x=__float2bfloat16_rn(v0); L.x=__float2bfloat16_rn(v0-__bfloat162float(H.x));
            H.y=__float2bfloat16_rn(v1); L.y=__float2bfloat16_rn(v1-__bfloat162float(H.y));
            *(unsigned*)&Oh[r*LDE+c] = *(unsigned*)&H;
            *(unsigned*)&Ol[r*LDE+c] = *(unsigned*)&L;
            if(erow && ((ewhich==0 && r==0) || (ewhich==1 && r==127))){
                erow[c]=v0; erow[c+1]=v1;
            }
        }
    }
}
__device__ __forceinline__ void cvt64(const float* s, __nv_bfloat16* dh, __nv_bfloat16* dl){
#pragma unroll
    for(int g=0; g<8; g++){
        float4 a=((const float4*)s)[2*g], b=((const float4*)s)[2*g+1];
        float f[8]={a.x,a.y,a.z,a.w,b.x,b.y,b.z,b.w};
        __align__(16) __nv_bfloat16 h[8], l[8];
#pragma unroll
        for(int i=0;i<8;i++){ h[i]=__float2bfloat16_rn(f[i]); l[i]=__float2bfloat16_rn(f[i]-__bfloat162float(h[i])); }
        ((uint4*)dh)[g]=*(const uint4*)h; ((uint4*)dl)[g]=*(const uint4*)l;
    }
}
__device__ __forceinline__ void pref_wmat(unsigned sb, unsigned reg,
                                          const __nv_bfloat16* wh, const __nv_bfloat16* wl, int tid){
#pragma unroll
    for(int i=0;i<16;i++){
        int c = tid + 256*i;
        int op = c>>11, e=c&2047, row=e>>4, col8=e&15;
        cpa(sb + reg + (unsigned)op*34816u + (unsigned)(row*272 + col8*16),
            (op? wl : wh) + (size_t)row*128 + col8*8);
    }
}
// stage 128x128 f32 rows into a region (row stride 528B = 132 f32)
__device__ __forceinline__ void stage_x(unsigned reg, const float* x, size_t row0, int tid){
#pragma unroll
    for(int i=0;i<16;i++){
        int c = tid + 256*i;
        int row=c>>5, col16=c&31;
        cpa(reg + (unsigned)(row*528 + col16*16), x + (row0+row)*128 + col16*4);
    }
}

// ================== persistent fused kernel =================================
__global__ __launch_bounds__(256,1) void kfused(
    const float* __restrict__ x,
    const float* __restrict__ Wq, const float* __restrict__ bq,
    const float* __restrict__ Wk, const float* __restrict__ bk,
    const float* __restrict__ Wv, const float* __restrict__ bv,
    float* __restrict__ out)
{
    extern __shared__ char sm[];
    __shared__ int s_item;
    unsigned sb = smem_u32(sm);
    const int tid=threadIdx.x, lane=tid&31, warp=tid>>5, wr=warp>>1, wc=warp&1;

    for(;;){
        if(tid==0) s_item = atomicAdd(&g_item, 1);
        __syncthreads();
        const int it = s_item;
        __syncthreads();
        if(it >= N_ITEMS) break;

        if(it < 8){
            // -------- role W: convert W matrices + Wq^T ---------------------
            int u = it*128 + tid;
            if(tid < 128){
                if(u < 768){
                    int m = u >> 8, e = u & 255, row = e >> 1, half = e & 1;
                    const float* W = m==0?Wq:(m==1?Wk:Wv);
                    size_t o = (size_t)m*16384 + (size_t)row*128 + half*64;
                    cvt64(W + (size_t)row*128 + half*64, g_w_hi+o, g_w_lo+o);
                } else {
                    int e = u - 768, d = e >> 1, half = e & 1, h0 = half*64;
                    float tmp[64];
#pragma unroll 16
                    for(int j=0; j<64; j++) tmp[j] = Wq[(size_t)(h0+j)*128 + d];
                    cvt64(tmp, g_wt_hi + (size_t)d*128 + h0, g_wt_lo + (size_t)d*128 + h0);
                }
            }
            __threadfence();
            __syncthreads();
            if(tid==0) atomicAdd(&g_wcnt, 1);
        }
        else if(it < 8+512){
            // -------- role A: x -> v,k proj -> partial C' -------------------
            const int idx=it-8, b=idx>>6, j=idx&63, m=j>>1, p=j&1;
            const size_t rbase=(size_t)b*S_LEN + j*128;
            __nv_bfloat16* Xh=(__nv_bfloat16*)(sm+R_XH); __nv_bfloat16* Xl=(__nv_bfloat16*)(sm+R_XL);
            float* biasv=(float*)(sm+R_EXT); float* biask=(float*)(sm+R_EXT+512);
            if(tid==0){ while(atomicAdd(&g_wcnt,0) < 8) __nanosleep(64); }
            __syncthreads();
            __threadfence();
            pref_wmat(sb, R_W, g_w_hi+2*16384, g_w_lo+2*16384, tid);   // Wv
            pref_wmat(sb, R_V, g_w_hi+1*16384, g_w_lo+1*16384, tid);   // Wk
            CPC();
            const int r=tid>>1, hf=tid&1;
            cvt64(x + (rbase+r)*128 + hf*64, Xh + r*LDE + hf*64, Xl + r*LDE + hf*64);
            if(tid<128) biasv[tid]=bv[tid]; else biask[tid-128]=bk[tid-128];
            CPW(0); __syncthreads();
            // v = x @ Wv^T
            float acc[2][8][4]; zacc(acc);
            pass3N(sb+R_XH, sb+R_XL, sb+R_WH, sb+R_WL, acc, wr, wc, lane);
            __syncthreads();
            frag_to_op(acc, (__nv_bfloat16*)(sm+R_WH), (__nv_bfloat16*)(sm+R_WL),
                       biasv, g_eV + ((size_t)(b*32+m)*2+p)*128, p, wr, wc, lane);  // V -> R_W
            __syncthreads();
            // k = x @ Wk^T
            zacc(acc);
            pass3N(sb+R_XH, sb+R_XL, sb+R_VH, sb+R_VL, acc, wr, wc, lane);
            __syncthreads();
            frag_to_op(acc, Xh, Xl, biask, g_eK + ((size_t)(b*32+m)*2+p)*128, p, wr, wc, lane); // K -> R_X
            __syncthreads();
            // partial C' for this 128-half (own slice, plain stores)
            zacc(acc);
            pass3T(sb+R_WH, sb+R_WL, sb+R_XH, sb+R_XL, acc, wr, wc, lane);
            float* cb = g_C + (size_t)((b*32+m)*2+p)*16384;
#pragma unroll
            for(int mt=0; mt<2; mt++)
#pragma unroll
            for(int nt=0; nt<8; nt++){
                int c = wc*64 + (lane&3)*2 + nt*8;
#pragma unroll
                for(int hh=0; hh<2; hh++){
                    int rr = wr*32 + (lane>>2) + mt*16 + hh*8;
                    *(float2*)(cb + (size_t)rr*128 + c) =
                        make_float2(acc[mt][nt][hh*2], acc[mt][nt][hh*2+1]);
                }
            }
            __threadfence();
            __syncthreads();
            if(tid==0) atomicAdd(&g_done[b*32+m], 1);
        }
        else {
            // -------- role B: G = M~ @ Wq ; out = scale*(x@G^T + c) ---------
            const int idx=it-520, b=idx>>5, n=idx&31;
            __nv_bfloat16* Xh=(__nv_bfloat16*)(sm+R_XH); __nv_bfloat16* Xl=(__nv_bfloat16*)(sm+R_XL);
            __nv_bfloat16* Vh=(__nv_bfloat16*)(sm+R_VH); __nv_bfloat16* Vl=(__nv_bfloat16*)(sm+R_VL);
            float* keL=(float*)(sm+R_EXT);      float* keR=(float*)(sm+R_EXT+512);
            float* veL=(float*)(sm+R_EXT+1024); float* veR=(float*)(sm+R_EXT+1536);
            float* bqs=(float*)(sm+R_EXT+2048); float* cs=(float*)(sm+R_EXT+2560);
            const size_t qbase=(size_t)b*S_LEN + n*256;
            if(tid==0){
                int mlo=(n>0)?n-1:n, mhi=(n<31)?n+1:n;
                for(int mm=mlo; mm<=mhi; mm++)
                    while(atomicAdd(&g_done[b*32+mm],0) < 2) __nanosleep(64);
            }
            __syncthreads();
            __threadfence();
            pref_wmat(sb, R_W, g_wt_hi, g_wt_lo, tid); CPC();       // g0: Wq^T
            stage_x(sb+R_X, x, qbase, tid); CPC();                  // g1: x half0 f32
            if(tid<128){
                bqs[tid]=bq[tid];
                keL[tid]=(n>0)?  g_eK[((size_t)(b*32+n-1)*2+0)*128+tid] : 0.f;
                keR[tid]=(n<31)? g_eK[((size_t)(b*32+n+1)*2+1)*128+tid] : 0.f;
            } else {
                int t2=tid-128;
                veL[t2]=(n>0)?  g_eV[((size_t)(b*32+n-1)*2+0)*128+t2] : 0.f;
                veR[t2]=(n<31)? g_eV[((size_t)(b*32+n+1)*2+1)*128+t2] : 0.f;
            }
            __syncthreads();
            const int r=tid>>1, hf=tid&1;
            {   // M~ = sum of 6 partial slices - edges ; c = bq.M~ ; cvt -> R_V
                const int slo=((n>0)?n-1:n)*2, shi=((n<31)?n+1:n)*2+1;
                float s[64];
#pragma unroll
                for(int q2=0;q2<64;q2++) s[q2]=0.f;
                for(int ss=slo; ss<=shi; ss++){
                    const float4* pp=(const float4*)(g_C+((size_t)(b*32*2+ss))*16384 + r*128 + hf*64);
#pragma unroll
                    for(int g=0; g<16; g++){ float4 v=pp[g]; s[g*4]+=v.x; s[g*4+1]+=v.y; s[g*4+2]+=v.z; s[g*4+3]+=v.w; }
                }
                float vl=veL[r], vr=veR[r], cpart=0.f;
#pragma unroll
                for(int q2=0;q2<64;q2++){
                    int col=hf*64+q2;
                    s[q2] -= vl*keL[col] + vr*keR[col];
                    cpart += bqs[col]*s[q2];
                }
                cpart += __shfl_xor_sync(0xffffffffu, cpart, 1);
                if(hf==0) cs[r]=cpart;
                __align__(16) __nv_bfloat16 h8[8], l8[8];
#pragma unroll
                for(int g=0; g<8; g++){
#pragma unroll
                    for(int i=0;i<8;i++){
                        float v=s[g*8+i];
                        h8[i]=__float2bfloat16_rn(v); l8[i]=__float2bfloat16_rn(v-__bfloat162float(h8[i]));
                    }
                    ((uint4*)(Vh + r*LDE + hf*64))[g]=*(const uint4*)h8;
                    ((uint4*)(Vl + r*LDE + hf*64))[g]=*(const uint4*)l8;
                }
            }
            CPW(0);                       // Wq^T + x0 in
            {   // cvt x0 f32(R_X staging) -> bf16 operand (in-place)
                float v[64];
                const float4* p4 = (const float4*)((const float*)(sm+R_X) + r*132 + hf*64);
#pragma unroll
                for(int g=0; g<16; g++){ float4 t=p4[g]; v[g*4]=t.x; v[g*4+1]=t.y; v[g*4+2]=t.z; v[g*4+3]=t.w; }
                __syncthreads();
                __align__(16) __nv_bfloat16 h8[8], l8[8];
#pragma unroll
                for(int g=0; g<8; g++){
#pragma unroll
                    for(int i=0;i<8;i++){
                        float vv=v[g*8+i];
                        h8[i]=__float2bfloat16_rn(vv); l8[i]=__float2bfloat16_rn(vv-__bfloat162float(h8[i]));
                    }
                    ((uint4*)(Xh + r*LDE + hf*64))[g]=*(const uint4*)h8;
                    ((uint4*)(Xl + r*LDE + hf*64))[g]=*(const uint4*)l8;
                }
            }
            __syncthreads();              // M~, x0 operands ready
            // G[hv][d] = M~ @ Wq
            float acc[2][8][4]; zacc(acc);
            pass3N(sb+R_VH, sb+R_VL, sb+R_WH, sb+R_WL, acc, wr, wc, lane);
            __syncthreads();
            stage_x(sb+R_W, x, qbase+128, tid); CPC();   // g2: x half1 -> R_W (dead)
            frag_to_op(acc, Vh, Vl, (const float*)0, (float*)0, 0, wr, wc, lane);    // G -> R_V
            __syncthreads();
            const float scale=0.08838834764831845f;
#pragma unroll
            for(int half=0; half<2; half++){
                zacc(acc);
                pass3N(sb+R_XH, sb+R_XL, sb+R_VH, sb+R_VL, acc, wr, wc, lane);
                float* ob = out + (qbase+half*128)*128;
#pragma unroll
                for(int mt=0; mt<2; mt++)
#pragma unroll
                for(int nt=0; nt<8; nt++){
                    int c = wc*64 + (lane&3)*2 + nt*8;
                    float c0=cs[c], c1=cs[c+1];
#pragma unroll
                    for(int hh=0; hh<2; hh++){
                        int rr = wr*32 + (lane>>2) + mt*16 + hh*8;
                        float2 o;
                        o.x = scale*(acc[mt][nt][hh*2]   + c0);
                        o.y = scale*(acc[mt][nt][hh*2+1] + c1);
                        *(float2*)(ob + (size_t)rr*128 + c) = o;
                    }
                }
                if(half==0){
                    CPW(0); __syncthreads();
                    float v[64];
                    const float4* p4 = (const float4*)((const float*)(sm+R_W) + r*132 + hf*64);
#pragma unroll
                    for(int g=0; g<16; g++){ float4 t=p4[g]; v[g*4]=t.x; v[g*4+1]=t.y; v[g*4+2]=t.z; v[g*4+3]=t.w; }
                    __align__(16) __nv_bfloat16 h8[8], l8[8];
#pragma unroll
                    for(int g=0; g<8; g++){
#pragma unroll
                        for(int i=0;i<8;i++){
                            float vv=v[g*8+i];
                            h8[i]=__float2bfloat16_rn(vv); l8[i]=__float2bfloat16_rn(vv-__bfloat162float(h8[i]));
                        }
                        ((uint4*)(Xh + r*LDE + hf*64))[g]=*(const uint4*)h8;
                        ((uint4*)(Xl + r*LDE + hf*64))[g]=*(const uint4*)l8;
                    }
                    __syncthreads();
                }
            }
            __syncthreads();   // protect smem before next queue item
        }
    }
}

// reset queue/flags for next graph replay (runs after kfused in same stream)
__global__ void kreset(){
    int t = threadIdx.x;
    if(t < NBATCH*NB) g_done[t] = 0;
    if(t == 0){ g_item = 0; g_wcnt = 0; }
}

// ---------------------------------------------------------------------------
extern "C" void kernel_launch(void* const* d_in, const int* in_sizes, int n_in,
                              void* d_out, int out_size)
{
    const float* x =(const float*)d_in[0];
    const float* Wq=(const float*)d_in[1]; const float* bq=(const float*)d_in[2];
    const float* Wk=(const float*)d_in[3]; const float* bk=(const float*)d_in[4];
    const float* Wv=(const float*)d_in[5]; const float* bv=(const float*)d_in[6];
    float* out=(float*)d_out;
    cudaFuncSetAttribute(kfused, cudaFuncAttributeMaxDynamicSharedMemorySize, SMEM_SZ);
    kfused<<<148, 256, SMEM_SZ>>>(x, Wq, bq, Wk, bk, Wv, bv, out);
    kreset<<<1, 256>>>();
}

// round 15
// speedup vs baseline: 1.1945x; 1.1945x over previous
#include <cuda_runtime.h>
#include <cuda_bf16.h>
#include <cstdint>

#define S_LEN 8192
#define NBATCH 8
#define DIM 128
#define NB 32
#define NROWS (NBATCH*S_LEN)
#define LDE 136      // bf16 elems per 272B operand row

// ---------------- scratch (static device arrays; allocation-free rule) -----
__device__ __align__(16) float g_C[(size_t)NBATCH*NB*DIM*DIM];   // C'[hv][hk] per 256-chunk
__device__ __align__(16) float g_eK[(size_t)NBATCH*NB*2*DIM];    // edge k rows (biased)
__device__ __align__(16) float g_eV[(size_t)NBATCH*NB*2*DIM];
__device__ __align__(16) __nv_bfloat16 g_w_hi[3*DIM*DIM];        // Wq,Wk,Wv (row-major [h][d])
__device__ __align__(16) __nv_bfloat16 g_w_lo[3*DIM*DIM];
__device__ __align__(16) __nv_bfloat16 g_wt_hi[DIM*DIM];         // Wq^T ([d][hq])
__device__ __align__(16) __nv_bfloat16 g_wt_lo[DIM*DIM];

// smem regions (both kernels): 3 x 68KB operand regions + ext
#define R_X 0
#define R_XH 0
#define R_XL 34816
#define R_W 69632
#define R_WH 69632
#define R_WL 104448
#define R_V 139264
#define R_VH 139264
#define R_VL 174080
#define R_EXT 208896
#define SMEM_SZ (R_EXT+3072)

// ---------------- helpers ---------------------------------------------------
__device__ __forceinline__ unsigned smem_u32(const void* p){
    unsigned a; asm("{ .reg .u64 t; cvta.to.shared.u64 t, %1; cvt.u32.u64 %0, t; }":"=r"(a):"l"(p)); return a;
}
__device__ __forceinline__ void ldm4(unsigned* r, unsigned addr){
    asm volatile("ldmatrix.sync.aligned.m8n8.x4.shared.b16 {%0,%1,%2,%3}, [%4];"
        : "=r"(r[0]),"=r"(r[1]),"=r"(r[2]),"=r"(r[3]) : "r"(addr));
}
__device__ __forceinline__ void ldm4t(unsigned* r, unsigned addr){
    asm volatile("ldmatrix.sync.aligned.m8n8.x4.trans.shared.b16 {%0,%1,%2,%3}, [%4];"
        : "=r"(r[0]),"=r"(r[1]),"=r"(r[2]),"=r"(r[3]) : "r"(addr));
}
__device__ __forceinline__ void mma16816(float* d, const unsigned* a, unsigned b0, unsigned b1){
    asm volatile("mma.sync.aligned.m16n8k16.row.col.f32.bf16.bf16.f32 "
        "{%0,%1,%2,%3}, {%4,%5,%6,%7}, {%8,%9}, {%0,%1,%2,%3};"
        : "+f"(d[0]),"+f"(d[1]),"+f"(d[2]),"+f"(d[3])
        : "r"(a[0]),"r"(a[1]),"r"(a[2]),"r"(a[3]), "r"(b0),"r"(b1));
}
__device__ __forceinline__ void cpa(unsigned d, const void* s){
    asm volatile("cp.async.cg.shared.global [%0], [%1], 16;"::"r"(d),"l"(s));
}
#define CPC() asm volatile("cp.async.commit_group;":::"memory")
#define CPW(n) asm volatile("cp.async.wait_group %0;"::"n"(n):"memory")

// merged 3-pass (AhBh + AhBl + AlBh), non-trans operands [row][k]
__device__ __forceinline__ void pass3N(unsigned aH, unsigned aL, unsigned bH, unsigned bL,
                                       float acc[2][8][4], int wr, int wc, int lane){
    unsigned aOff = (unsigned)((wr*32 + (lane&15))*272) + ((lane>>4)<<4);
    unsigned bOff = (unsigned)((wc*64 + (lane&7) + ((lane>>4)<<3))*272) + (((lane>>3)&1)<<4);
#pragma unroll
    for(int ks=0; ks<8; ks++){
        unsigned ah0[4], ah1[4], al0[4], al1[4], bh[4][4], bl[4][4];
        ldm4(ah0, aH + aOff + ks*32);
        ldm4(ah1, aH + aOff + 16*272 + ks*32);
        ldm4(al0, aL + aOff + ks*32);
        ldm4(al1, aL + aOff + 16*272 + ks*32);
#pragma unroll
        for(int n2=0; n2<4; n2++){
            ldm4(bh[n2], bH + bOff + n2*16*272 + ks*32);
            ldm4(bl[n2], bL + bOff + n2*16*272 + ks*32);
        }
#pragma unroll
        for(int nt=0; nt<8; nt++){
            unsigned b0 = bh[nt>>1][(nt&1)*2], b1 = bh[nt>>1][(nt&1)*2+1];
            mma16816(acc[0][nt], ah0, b0, b1);
            mma16816(acc[1][nt], ah1, b0, b1);
        }
#pragma unroll
        for(int nt=0; nt<8; nt++){
            unsigned c0 = bl[nt>>1][(nt&1)*2], c1 = bl[nt>>1][(nt&1)*2+1];
            mma16816(acc[0][nt], ah0, c0, c1);
            mma16816(acc[1][nt], ah1, c0, c1);
        }
#pragma unroll
        for(int nt=0; nt<8; nt++){
            unsigned b0 = bh[nt>>1][(nt&1)*2], b1 = bh[nt>>1][(nt&1)*2+1];
            mma16816(acc[0][nt], al0, b0, b1);
            mma16816(acc[1][nt], al1, b0, b1);
        }
    }
}
// merged 3-pass, trans operands stored [t][m]/[t][n]
__device__ __forceinline__ void pass3T(unsigned aH, unsigned aL, unsigned bH, unsigned bL,
                                       float acc[2][8][4], int wr, int wc, int lane){
    unsigned row = (unsigned)((lane&7) + ((lane>>4)<<3));
    unsigned csel = (unsigned)((lane>>3)&1);
    unsigned aOff = row*272 + (unsigned)(wr*32 + csel*8)*2;
    unsigned bOff = row*272 + (unsigned)(wc*64 + csel*8)*2;
#pragma unroll
    for(int ks=0; ks<8; ks++){
        unsigned base = (unsigned)ks*4352;
        unsigned ah0[4], ah1[4], al0[4], al1[4], bh[4][4], bl[4][4];
        ldm4t(ah0, aH + aOff + base);
        ldm4t(ah1, aH + aOff + base + 32);
        ldm4t(al0, aL + aOff + base);
        ldm4t(al1, aL + aOff + base + 32);
#pragma unroll
        for(int g=0; g<4; g++){
            ldm4t(bh[g], bH + bOff + base + g*32);
            ldm4t(bl[g], bL + bOff + base + g*32);
        }
#pragma unroll
        for(int nt=0; nt<8; nt++){
            int g=nt>>1, sub=nt&1;
            unsigned b0 = bh[g][sub], b1 = bh[g][sub+2];
            mma16816(acc[0][nt], ah0, b0, b1);
            mma16816(acc[1][nt], ah1, b0, b1);
        }
#pragma unroll
        for(int nt=0; nt<8; nt++){
            int g=nt>>1, sub=nt&1;
            unsigned c0 = bl[g][sub], c1 = bl[g][sub+2];
            mma16816(acc[0][nt], ah0, c0, c1);
            mma16816(acc[1][nt], ah1, c0, c1);
        }
#pragma unroll
        for(int nt=0; nt<8; nt++){
            int g=nt>>1, sub=nt&1;
            unsigned b0 = bh[g][sub], b1 = bh[g][sub+2];
            mma16816(acc[0][nt], al0, b0, b1);
            mma16816(acc[1][nt], al1, b0, b1);
        }
    }
}
__device__ __forceinline__ void zacc(float acc[2][8][4]){
#pragma unroll
    for(int a=0;a<2;a++)
#pragma unroll
    for(int b=0;b<8;b++){acc[a][b][0]=acc[a][b][1]=acc[a][b][2]=acc[a][b][3]=0.f;}
}
__device__ __forceinline__ void frag_to_op(float acc[2][8][4], __nv_bfloat16* Oh, __nv_bfloat16* Ol,
                                           const float* bias, float* erow, int ewhich,
                                           int wr, int wc, int lane){
#pragma unroll
    for(int mt=0; mt<2; mt++)
#pragma unroll
    for(int nt=0; nt<8; nt++){
        int c = wc*64 + (lane&3)*2 + nt*8;
        float b0 = bias? bias[c]   : 0.f;
        float b1 = bias? bias[c+1] : 0.f;
#pragma unroll
        for(int hh=0; hh<2; hh++){
            int r = wr*32 + (lane>>2) + mt*16 + hh*8;
            float v0 = acc[mt][nt][hh*2]   + b0;
            float v1 = acc[mt][nt][hh*2+1] + b1;
            __nv_bfloat162 H, L;
            H.x=__float2bfloat16_rn(v0); L.x=__float2bfloat16_rn(v0-__bfloat162float(H.x));
            H.y=__float2bfloat16_rn(v1); L.y=__float2bfloat16_rn(v1-__bfloat162float(H.y));
            *(unsigned*)&Oh[r*LDE+c] = *(unsigned*)&H;
            *(unsigned*)&Ol[r*LDE+c] = *(unsigned*)&L;
            if(erow && ((ewhich==0 && r==0) || (ewhich==1 && r==127))){
                erow[c]=v0; erow[c+1]=v1;
            }
        }
    }
}
__device__ __forceinline__ void cvt64(const float* s, __nv_bfloat16* dh, __nv_bfloat16* dl){
#pragma unroll
    for(int g=0; g<8; g++){
        float4 a=((const float4*)s)[2*g], b=((const float4*)s)[2*g+1];
        float f[8]={a.x,a.y,a.z,a.w,b.x,b.y,b.z,b.w};
        __align__(16) __nv_bfloat16 h[8], l[8];
#pragma unroll
        for(int i=0;i<8;i++){ h[i]=__float2bfloat16_rn(f[i]); l[i]=__float2bfloat16_rn(f[i]-__bfloat162float(h[i])); }
        ((uint4*)dh)[g]=*(const uint4*)h; ((uint4*)dl)[g]=*(const uint4*)l;
    }
}
__device__ __forceinline__ void pref_wmat(unsigned sb, unsigned reg,
                                          const __nv_bfloat16* wh, const __nv_bfloat16* wl, int tid){
#pragma unroll
    for(int i=0;i<16;i++){
        int c = tid + 256*i;
        int op = c>>11, e=c&2047, row=e>>4, col8=e&15;
        cpa(sb + reg + (unsigned)op*34816u + (unsigned)(row*272 + col8*16),
            (op? wl : wh) + (size_t)row*128 + col8*8);
    }
}
// stage 128x128 f32 rows into a region (row stride 528B = 132 f32)
__device__ __forceinline__ void stage_x(unsigned reg, const float* x, size_t row0, int tid){
#pragma unroll
    for(int i=0;i<16;i++){
        int c = tid + 256*i;
        int row=c>>5, col16=c&31;
        cpa(reg + (unsigned)(row*528 + col16*16), x + (row0+row)*128 + col16*4);
    }
}

// ============== k0w: pre-convert W (+ Wq^T), parallel over 1024 units =======
__global__ void k0w(const float* __restrict__ Wq, const float* __restrict__ Wk,
                    const float* __restrict__ Wv){
    int u = blockIdx.x*128 + threadIdx.x;          // 0..1023
    if(u < 768){
        int m = u >> 8, e = u & 255, row = e >> 1, half = e & 1;
        const float* W = m==0?Wq:(m==1?Wk:Wv);
        size_t o = (size_t)m*16384 + (size_t)row*128 + half*64;
        cvt64(W + (size_t)row*128 + half*64, g_w_hi+o, g_w_lo+o);
    } else {
        int e = u - 768, d = e >> 1, half = e & 1, h0 = half*64;
        float tmp[64];
#pragma unroll 16
        for(int j=0; j<64; j++) tmp[j] = Wq[(size_t)(h0+j)*128 + d];
        cvt64(tmp, g_wt_hi + (size_t)d*128 + h0, g_wt_lo + (size_t)d*128 + h0);
    }
}

// ============== kA: full 256-chunk per CTA: v,k proj -> C' (no atomics) =====
#define A_BIASV (R_EXT)
#define A_BIASK (R_EXT+512)
__global__ __launch_bounds__(256,1) void kA(const float* __restrict__ x,
    const float* __restrict__ bk, const float* __restrict__ bv)
{
    extern __shared__ char sm[];
    unsigned sb = smem_u32(sm);
    const int tid=threadIdx.x, lane=tid&31, warp=tid>>5, wr=warp>>1, wc=warp&1;
    const int b=blockIdx.x>>5, m=blockIdx.x&31;
    __nv_bfloat16* Xh=(__nv_bfloat16*)(sm+R_XH); __nv_bfloat16* Xl=(__nv_bfloat16*)(sm+R_XL);
    float* biasv=(float*)(sm+A_BIASV); float* biask=(float*)(sm+A_BIASK);
    const int r=tid>>1, hf=tid&1;
    float* cb = g_C + (size_t)(b*32+m)*16384;

    pref_wmat(sb, R_W, g_w_hi+2*16384, g_w_lo+2*16384, tid);   // Wv
    pref_wmat(sb, R_V, g_w_hi+1*16384, g_w_lo+1*16384, tid);   // Wk (persists both halves)
    CPC();
    if(tid<128) biasv[tid]=bv[tid]; else biask[tid-128]=bk[tid-128];

#pragma unroll 1
    for(int p=0; p<2; p++){
        const size_t rbase=(size_t)b*S_LEN + (m*2+p)*128;
        // x -> R_X (direct cvt; R_X is free: p0 trivially, p1 after tail sync below)
        cvt64(x + (rbase+r)*128 + hf*64, Xh + r*LDE + hf*64, Xl + r*LDE + hf*64);
        CPW(0); __syncthreads();                       // W in, X written
        // v = x @ Wv^T
        float acc[2][8][4]; zacc(acc);
        pass3N(sb+R_XH, sb+R_XL, sb+R_WH, sb+R_WL, acc, wr, wc, lane);
        __syncthreads();                               // done reading Wv
        frag_to_op(acc, (__nv_bfloat16*)(sm+R_WH), (__nv_bfloat16*)(sm+R_WL),
                   biasv, g_eV + ((size_t)(b*32+m)*2+p)*128, p, wr, wc, lane);  // V -> R_W
        __syncthreads();
        // k = x @ Wk^T  (Wk in R_V, intact)
        zacc(acc);
        pass3N(sb+R_XH, sb+R_XL, sb+R_VH, sb+R_VL, acc, wr, wc, lane);
        __syncthreads();                               // done reading x
        frag_to_op(acc, Xh, Xl, biask, g_eK + ((size_t)(b*32+m)*2+p)*128, p, wr, wc, lane); // K -> R_X
        __syncthreads();
        // C' partial for this half
        zacc(acc);
        pass3T(sb+R_WH, sb+R_WL, sb+R_XH, sb+R_XL, acc, wr, wc, lane);
        __syncthreads();                               // all warps done with R_W/R_X
        if(p==1){                                      // prefetch Wv for... (none) — skip
        } else {
            pref_wmat(sb, R_W, g_w_hi+2*16384, g_w_lo+2*16384, tid);  // re-fetch Wv for half1
            CPC();
        }
        // store (p0) / accumulate (p1) partial C' — same thread, same addresses
#pragma unroll
        for(int mt=0; mt<2; mt++)
#pragma unroll
        for(int nt=0; nt<8; nt++){
            int c = wc*64 + (lane&3)*2 + nt*8;
#pragma unroll
            for(int hh=0; hh<2; hh++){
                int rr = wr*32 + (lane>>2) + mt*16 + hh*8;
                float2 v = make_float2(acc[mt][nt][hh*2], acc[mt][nt][hh*2+1]);
                float2* dst = (float2*)(cb + (size_t)rr*128 + c);
                if(p==1){ float2 o = *dst; v.x += o.x; v.y += o.y; }
                *dst = v;
            }
        }
    }
}

// ============== kB: G = M~ @ Wq ; out = scale*(x@G^T + c) ==================
#define B_KEL (R_EXT)
#define B_KER (R_EXT+512)
#define B_VEL (R_EXT+1024)
#define B_VER (R_EXT+1536)
#define B_BQ  (R_EXT+2048)
#define B_CS  (R_EXT+2560)
__global__ __launch_bounds__(256,1) void kB(float* __restrict__ out,
    const float* __restrict__ x, const float* __restrict__ bq)
{
    extern __shared__ char sm[];
    unsigned sb = smem_u32(sm);
    const int tid=threadIdx.x, lane=tid&31, warp=tid>>5, wr=warp>>1, wc=warp&1;
    const int b=blockIdx.x>>5, n=blockIdx.x&31;
    __nv_bfloat16* Xh=(__nv_bfloat16*)(sm+R_XH); __nv_bfloat16* Xl=(__nv_bfloat16*)(sm+R_XL);
    __nv_bfloat16* Vh=(__nv_bfloat16*)(sm+R_VH); __nv_bfloat16* Vl=(__nv_bfloat16*)(sm+R_VL);
    float* keL=(float*)(sm+B_KEL); float* keR=(float*)(sm+B_KER);
    float* veL=(float*)(sm+B_VEL); float* veR=(float*)(sm+B_VER);
    float* bqs=(float*)(sm+B_BQ);  float* cs=(float*)(sm+B_CS);
    const size_t qbase=(size_t)b*S_LEN + n*256;
    pref_wmat(sb, R_W, g_wt_hi, g_wt_lo, tid); CPC();       // g0: Wq^T
    stage_x(sb+R_X, x, qbase, tid); CPC();                  // g1: x half0 f32
    if(tid<128){
        bqs[tid]=bq[tid];
        keL[tid]=(n>0)?  g_eK[((size_t)(b*32+n-1)*2+0)*128+tid] : 0.f;
        keR[tid]=(n<31)? g_eK[((size_t)(b*32+n+1)*2+1)*128+tid] : 0.f;
    } else {
        int t2=tid-128;
        veL[t2]=(n>0)?  g_eV[((size_t)(b*32+n-1)*2+0)*128+t2] : 0.f;
        veR[t2]=(n<31)? g_eV[((size_t)(b*32+n+1)*2+1)*128+t2] : 0.f;
    }
    __syncthreads();
    const int r=tid>>1, hf=tid&1;
    {   // M~ = Csum - veL(x)keL - veR(x)keR ; c[hv] = bq . M~[hv] ; cvt -> R_V
        const int mlo=(n>0)?n-1:0, mhi=(n<31)?n+1:31;
        float s[64];
#pragma unroll
        for(int q2=0;q2<64;q2++) s[q2]=0.f;
        for(int mm=mlo; mm<=mhi; mm++){
            const float4* pp=(const float4*)(g_C+(size_t)(b*32+mm)*16384 + r*128 + hf*64);
#pragma unroll
            for(int g=0; g<16; g++){ float4 v=pp[g]; s[g*4]+=v.x; s[g*4+1]+=v.y; s[g*4+2]+=v.z; s[g*4+3]+=v.w; }
        }
        float vl=veL[r], vr=veR[r], cpart=0.f;
#pragma unroll
        for(int q2=0;q2<64;q2++){
            int col=hf*64+q2;
            s[q2] -= vl*keL[col] + vr*keR[col];
            cpart += bqs[col]*s[q2];
        }
        cpart += __shfl_xor_sync(0xffffffffu, cpart, 1);
        if(hf==0) cs[r]=cpart;
        __align__(16) __nv_bfloat16 h8[8], l8[8];
#pragma unroll
        for(int g=0; g<8; g++){
#pragma unroll
            for(int i=0;i<8;i++){
                float v=s[g*8+i];
                h8[i]=__float2bfloat16_rn(v); l8[i]=__float2bfloat16_rn(v-__bfloat162float(h8[i]));
            }
            ((uint4*)(Vh + r*LDE + hf*64))[g]=*(const uint4*)h8;
            ((uint4*)(Vl + r*LDE + hf*64))[g]=*(const uint4*)l8;
        }
    }
    CPW(0);                       // Wq^T + x0 in
    {   // cvt x0 f32(R_X staging) -> bf16 operand (in-place): read, sync, write
        float v[64];
        const float4* p4 = (const float4*)((const float*)(sm+R_X) + r*132 + hf*64);
#pragma unroll
        for(int g=0; g<16; g++){ float4 t=p4[g]; v[g*4]=t.x; v[g*4+1]=t.y; v[g*4+2]=t.z; v[g*4+3]=t.w; }
        __syncthreads();
        __align__(16) __nv_bfloat16 h8[8], l8[8];
#pragma unroll
        for(int g=0; g<8; g++){
#pragma unroll
            for(int i=0;i<8;i++){
                float vv=v[g*8+i];
                h8[i]=__float2bfloat16_rn(vv); l8[i]=__float2bfloat16_rn(vv-__bfloat162float(h8[i]));
            }
            ((uint4*)(Xh + r*LDE + hf*64))[g]=*(const uint4*)h8;
            ((uint4*)(Xl + r*LDE + hf*64))[g]=*(const uint4*)l8;
        }
    }
    __syncthreads();              // M~, x0 operands ready
    // G[hv][d] = M~ @ Wq : A=R_V, B=R_W
    float acc[2][8][4]; zacc(acc);
    pass3N(sb+R_VH, sb+R_VL, sb+R_WH, sb+R_WL, acc, wr, wc, lane);
    __syncthreads();              // done reading M~ + Wq^T
    stage_x(sb+R_W, x, qbase+128, tid); CPC();   // g2: x half1 -> R_W (dead)
    frag_to_op(acc, Vh, Vl, (const float*)0, (float*)0, 0, wr, wc, lane);    // G -> R_V
    __syncthreads();
    const float scale=0.08838834764831845f;
#pragma unroll
    for(int half=0; half<2; half++){
        // out_half = x @ G^T
        zacc(acc);
        pass3N(sb+R_XH, sb+R_XL, sb+R_VH, sb+R_VL, acc, wr, wc, lane);
        float* ob = out + (qbase+half*128)*128;
#pragma unroll
        for(int mt=0; mt<2; mt++)
#pragma unroll
        for(int nt=0; nt<8; nt++){
            int c = wc*64 + (lane&3)*2 + nt*8;
            float c0=cs[c], c1=cs[c+1];
#pragma unroll
            for(int hh=0; hh<2; hh++){
                int rr = wr*32 + (lane>>2) + mt*16 + hh*8;
                float2 o;
                o.x = scale*(acc[mt][nt][hh*2]   + c0);
                o.y = scale*(acc[mt][nt][hh*2+1] + c1);
                *(float2*)(ob + (size_t)rr*128 + c) = o;
            }
        }
        if(half==0){
            CPW(0); __syncthreads();          // x1 staged; out0 done reading R_X
            float v[64];
            const float4* p4 = (const float4*)((const float*)(sm+R_W) + r*132 + hf*64);
#pragma unroll
            for(int g=0; g<16; g++){ float4 t=p4[g]; v[g*4]=t.x; v[g*4+1]=t.y; v[g*4+2]=t.z; v[g*4+3]=t.w; }
            __align__(16) __nv_bfloat16 h8[8], l8[8];
#pragma unroll
            for(int g=0; g<8; g++){
#pragma unroll
                for(int i=0;i<8;i++){
                    float vv=v[g*8+i];
                    h8[i]=__float2bfloat16_rn(vv); l8[i]=__float2bfloat16_rn(vv-__bfloat162float(h8[i]));
                }
                ((uint4*)(Xh + r*LDE + hf*64))[g]=*(const uint4*)h8;
                ((uint4*)(Xl + r*LDE + hf*64))[g]=*(const uint4*)l8;
            }
            __syncthreads();
        }
    }
}

// ---------------------------------------------------------------------------
extern "C" void kernel_launch(void* const* d_in, const int* in_sizes, int n_in,
                              void* d_out, int out_size)
{
    const float* x =(const float*)d_in[0];
    const float* Wq=(const float*)d_in[1]; const float* bq=(const float*)d_in[2];
    const float* Wk=(const float*)d_in[3]; const float* bk=(const float*)d_in[4];
    const float* Wv=(const float*)d_in[5]; const float* bv=(const float*)d_in[6];
    float* out=(float*)d_out;
    cudaFuncSetAttribute(kA, cudaFuncAttributeMaxDynamicSharedMemorySize, SMEM_SZ);
    cudaFuncSetAttribute(kB, cudaFuncAttributeMaxDynamicSharedMemorySize, SMEM_SZ);
    k0w<<<8,128>>>(Wq,Wk,Wv);
    kA<<<NBATCH*NB,256,SMEM_SZ>>>(x,bk,bv);
    kB<<<NBATCH*NB,256,SMEM_SZ>>>(out,x,bq);
}